// round 1
// baseline (speedup 1.0000x reference)
#include <cuda_runtime.h>
#include <cuda_bf16.h>

// loss = sum_{b,c,s,h,w} (out[b,c,2s,h,w] - target[b,c,2s+1,h,w])^2 / (C*H*Wd * W/2)
// B=8, C=32, W=16 (s=0..7), H=128, Wd=128.
//
// Used elements per tensor: N = 8*32*8*16384 = 33,554,432  (N4 = N/4 float4)
// Address map (element e): g = e>>14, hw = e&16383
//   out_addr = (g<<15) + hw ; tgt_addr = out_addr + 16384
// In float4 units (e4): g = e4>>12, hw4 = e4&4095
//   out4 = (g<<13) + hw4   ; tgt4 = out4 + 4096

#define NBLOCKS 2048
#define NTHREADS 256

__device__ float g_partials[NBLOCKS];

__global__ __launch_bounds__(NTHREADS) void cont_loss_partial_kernel(
    const float4* __restrict__ out4, const float4* __restrict__ tgt4)
{
    const long long N4 = 8388608LL;  // 33,554,432 / 4
    long long stride = (long long)gridDim.x * blockDim.x;
    long long i = (long long)blockIdx.x * blockDim.x + threadIdx.x;

    float acc = 0.0f;
    for (; i < N4; i += stride) {
        long long g   = i >> 12;
        long long hw4 = i & 4095;
        long long oa  = (g << 13) + hw4;
        float4 o = out4[oa];
        float4 t = tgt4[oa + 4096];
        float d0 = o.x - t.x;
        float d1 = o.y - t.y;
        float d2 = o.z - t.z;
        float d3 = o.w - t.w;
        acc = fmaf(d0, d0, acc);
        acc = fmaf(d1, d1, acc);
        acc = fmaf(d2, d2, acc);
        acc = fmaf(d3, d3, acc);
    }

    // deterministic block reduction
    __shared__ float sbuf[NTHREADS];
    sbuf[threadIdx.x] = acc;
    __syncthreads();
    #pragma unroll
    for (int ofs = NTHREADS / 2; ofs > 0; ofs >>= 1) {
        if (threadIdx.x < ofs) sbuf[threadIdx.x] += sbuf[threadIdx.x + ofs];
        __syncthreads();
    }
    if (threadIdx.x == 0) g_partials[blockIdx.x] = sbuf[0];
}

__global__ __launch_bounds__(NTHREADS) void cont_loss_final_kernel(float* __restrict__ out)
{
    // Sum 2048 partials deterministically in double, apply scale.
    __shared__ double sbuf[NTHREADS];
    double acc = 0.0;
    for (int i = threadIdx.x; i < NBLOCKS; i += NTHREADS)
        acc += (double)g_partials[i];
    sbuf[threadIdx.x] = acc;
    __syncthreads();
    #pragma unroll
    for (int ofs = NTHREADS / 2; ofs > 0; ofs >>= 1) {
        if (threadIdx.x < ofs) sbuf[threadIdx.x] += sbuf[threadIdx.x + ofs];
        __syncthreads();
    }
    if (threadIdx.x == 0) {
        // divisor: mean over (C,H,Wd)=524288, then / half_win(=8)
        const double scale = 1.0 / (524288.0 * 8.0);
        out[0] = (float)(sbuf[0] * scale);
    }
}

extern "C" void kernel_launch(void* const* d_in, const int* in_sizes, int n_in,
                              void* d_out, int out_size)
{
    const float4* out4 = (const float4*)d_in[0];
    const float4* tgt4 = (const float4*)d_in[1];
    float* o = (float*)d_out;

    cont_loss_partial_kernel<<<NBLOCKS, NTHREADS>>>(out4, tgt4);
    cont_loss_final_kernel<<<1, NTHREADS>>>(o);
}